// round 4
// baseline (speedup 1.0000x reference)
#include <cuda_runtime.h>
#include <cstddef>

// ----------------------------------------------------------------------------
// Problem constants (HetGraphModel)
// ----------------------------------------------------------------------------
#define N_NODES  100000
#define N_EDGES  500000
#define N_REL    3
#define N_LAYERS 2
#define F_IN     300
#define H_DIM    256
#define C_OUT    23

// ----------------------------------------------------------------------------
// Scratch (device globals — no allocation allowed)
// ----------------------------------------------------------------------------
__device__ float g_h  [(size_t)N_NODES * H_DIM];
__device__ float g_res[(size_t)N_NODES * H_DIM];
__device__ float g_m  [(size_t)N_NODES * H_DIM];
__device__ float g_acc[(size_t)N_NODES * H_DIM];
__device__ float g_rs_out[N_REL * N_NODES];
__device__ float g_rs_in [N_REL * N_NODES];
__device__ float g_stat  [2 * H_DIM];

// ----------------------------------------------------------------------------
// Helpers
// ----------------------------------------------------------------------------
__device__ __forceinline__ void red_add_v4(float4* addr, float4 v) {
    asm volatile("red.global.add.v4.f32 [%0], {%1, %2, %3, %4};"
                 :: "l"(addr), "f"(v.x), "f"(v.y), "f"(v.z), "f"(v.w)
                 : "memory");
}

__global__ void k_zero4(float4* __restrict__ p, int n4) {
    int i = blockIdx.x * blockDim.x + threadIdx.x;
    if (i < n4) p[i] = make_float4(0.f, 0.f, 0.f, 0.f);
}

// Degree counts (as float) for all relations at once.
// esrc/edst are flat [R*E]; entry i belongs to relation i / E.
__global__ void k_deg(const int* __restrict__ esrc, const int* __restrict__ edst,
                      float* __restrict__ deg_out, float* __restrict__ deg_in) {
    int i = blockIdx.x * blockDim.x + threadIdx.x;
    if (i < N_REL * N_EDGES) {
        int r = i / N_EDGES;
        atomicAdd(&deg_out[r * N_NODES + esrc[i]], 1.0f);
        atomicAdd(&deg_in [r * N_NODES + edst[i]], 1.0f);
    }
}

__global__ void k_rsqrt_clip(float* __restrict__ p, int n) {
    int i = blockIdx.x * blockDim.x + threadIdx.x;
    if (i < n) p[i] = rsqrtf(fmaxf(p[i], 1.0f));
}

// ----------------------------------------------------------------------------
// Tiled fp32 GEMM:  C[M,Nout] (=|+)= scaleRow(A)[M,K] @ W[K,Nout] + bias
// BM=128, BK=16, BN_/TN_ templated. 256 threads, thread computes TM x TN_.
// ----------------------------------------------------------------------------
template <int BN_, int TN_>
__global__ __launch_bounds__(256, 2)
void k_gemm(const float* __restrict__ A, const float* __restrict__ rowscale,
            const float* __restrict__ W, const float* __restrict__ bias,
            float* __restrict__ C, int M, int K, int Nout, int accumulate) {
    constexpr int BM = 128;
    constexpr int BK = 16;
    constexpr int TM = 8;

    __shared__ float As[BK][BM + 4];
    __shared__ float Bs[BK][BN_ + 4];

    const int tid = threadIdx.x;
    const int tx = tid & 15;   // 16 column groups
    const int ty = tid >> 4;   // 16 row groups
    const int m0 = blockIdx.y * BM;
    const int n0 = blockIdx.x * BN_;

    float acc[TM][TN_];
#pragma unroll
    for (int i = 0; i < TM; i++)
#pragma unroll
        for (int j = 0; j < TN_; j++) acc[i][j] = 0.f;

    for (int k0 = 0; k0 < K; k0 += BK) {
        // Load A tile (BM x BK), transposed into As[k][row]
#pragma unroll
        for (int t = 0; t < (BM * BK) / 256; t++) {
            int lin = tid + t * 256;
            int row = lin >> 4;
            int kk  = lin & 15;
            int gr = m0 + row, gk = k0 + kk;
            float v = 0.f;
            if (gr < M && gk < K) {
                v = A[(size_t)gr * K + gk];
                if (rowscale) v *= rowscale[gr];
            }
            As[kk][row] = v;
        }
        // Load B tile (BK x BN_)
#pragma unroll
        for (int t = 0; t < (BN_ * BK) / 256; t++) {
            int lin = tid + t * 256;
            int kr  = lin / BN_;
            int col = lin % BN_;
            int gk = k0 + kr, gc = n0 + col;
            Bs[kr][col] = (gk < K && gc < Nout) ? W[(size_t)gk * Nout + gc] : 0.f;
        }
        __syncthreads();

#pragma unroll
        for (int kk = 0; kk < BK; kk++) {
            float ra[TM], rb[TN_];
#pragma unroll
            for (int i = 0; i < TM; i++) ra[i] = As[kk][ty * TM + i];
#pragma unroll
            for (int j = 0; j < TN_; j++) rb[j] = Bs[kk][tx * TN_ + j];
#pragma unroll
            for (int i = 0; i < TM; i++)
#pragma unroll
                for (int j = 0; j < TN_; j++)
                    acc[i][j] += ra[i] * rb[j];
        }
        __syncthreads();
    }

    // Epilogue
#pragma unroll
    for (int i = 0; i < TM; i++) {
        int gr = m0 + ty * TM + i;
        if (gr >= M) continue;
#pragma unroll
        for (int j = 0; j < TN_; j++) {
            int gc = n0 + tx * TN_ + j;
            if (gc >= Nout) continue;
            float v = acc[i][j] + (bias ? bias[gc] : 0.f);
            size_t idx = (size_t)gr * Nout + gc;
            if (accumulate) v += C[idx];
            C[idx] = v;
        }
    }
}

// ----------------------------------------------------------------------------
// BatchNorm: per-column sum / sumsq, then normalize + activation in place.
// ----------------------------------------------------------------------------
#define BN_ROWS 256
__global__ void k_bnstat(const float* __restrict__ h, float* __restrict__ stat, int M) {
    int col = threadIdx.x;                  // blockDim.x == H_DIM
    int r0 = blockIdx.x * BN_ROWS;
    int rend = min(r0 + BN_ROWS, M);
    float s = 0.f, s2 = 0.f;
    for (int r = r0; r < rend; r++) {
        float v = h[(size_t)r * H_DIM + col];
        s += v; s2 += v * v;
    }
    atomicAdd(&stat[col], s);
    atomicAdd(&stat[H_DIM + col], s2);
}

// act: 1 = relu, 2 = leaky_relu(0.01)
__global__ void k_bnact(float* __restrict__ h, const float* __restrict__ stat,
                        const float* __restrict__ g, const float* __restrict__ b,
                        int M, int act) {
    size_t i = (size_t)blockIdx.x * blockDim.x + threadIdx.x;
    if (i >= (size_t)M * H_DIM) return;
    int col = (int)(i & (H_DIM - 1));
    float invM = 1.f / (float)M;
    float mean = stat[col] * invM;
    float var  = stat[H_DIM + col] * invM - mean * mean;
    float v = (h[i] - mean) * rsqrtf(var + 1e-5f) * g[col] + b[col];
    if (act == 1)      v = fmaxf(v, 0.f);
    else if (act == 2) v = (v > 0.f) ? v : 0.01f * v;
    h[i] = v;
}

// h_new = acc/3 + res
__global__ void k_combine(const float4* __restrict__ acc, const float4* __restrict__ res,
                          float4* __restrict__ h, int n4) {
    int i = blockIdx.x * blockDim.x + threadIdx.x;
    if (i < n4) {
        float4 a = acc[i], r = res[i];
        h[i] = make_float4(a.x * (1.f / 3.f) + r.x, a.y * (1.f / 3.f) + r.y,
                           a.z * (1.f / 3.f) + r.z, a.w * (1.f / 3.f) + r.w);
    }
}

// ----------------------------------------------------------------------------
// Edge scatter: m[dst] += h[src] * rs_out[src]   (one warp per edge, v4 reds)
// ----------------------------------------------------------------------------
#define EPW 8
__global__ void k_scatter(const int* __restrict__ src, const int* __restrict__ dst,
                          const float* __restrict__ rs_out,
                          const float* __restrict__ h, float* __restrict__ m) {
    int warp = (blockIdx.x * blockDim.x + threadIdx.x) >> 5;
    int lane = threadIdx.x & 31;
    int e0 = warp * EPW;
    for (int j = 0; j < EPW; j++) {
        int e = e0 + j;
        if (e >= N_EDGES) return;
        int s = src[e];
        int d = dst[e];
        float sc = rs_out[s];
        const float4* hr = reinterpret_cast<const float4*>(h) + (size_t)s * (H_DIM / 4);
        float4*       mr = reinterpret_cast<float4*>(m)       + (size_t)d * (H_DIM / 4);
        float4 a = hr[lane];
        float4 b = hr[lane + 32];
        a.x *= sc; a.y *= sc; a.z *= sc; a.w *= sc;
        b.x *= sc; b.y *= sc; b.z *= sc; b.w *= sc;
        red_add_v4(mr + lane, a);
        red_add_v4(mr + lane + 32, b);
    }
}

// ----------------------------------------------------------------------------
// Host-side orchestration
// ----------------------------------------------------------------------------
static inline void zero4(float* p, size_t n) {
    int n4 = (int)(n / 4);
    k_zero4<<<(n4 + 255) / 256, 256>>>((float4*)p, n4);
}

static inline void run_gemm_H(const float* A, const float* rs, const float* W,
                              const float* bias, float* C, int M, int K, int accum) {
    dim3 grid(H_DIM / 128, (M + 127) / 128);
    k_gemm<128, 8><<<grid, 256>>>(A, rs, W, bias, C, M, K, H_DIM, accum);
}

static inline void run_bn(float* h, const float* g, const float* b, int act, float* stat) {
    zero4(stat, 2 * H_DIM);
    k_bnstat<<<(N_NODES + BN_ROWS - 1) / BN_ROWS, H_DIM>>>(h, stat, N_NODES);
    size_t tot = (size_t)N_NODES * H_DIM;
    k_bnact<<<(unsigned)((tot + 255) / 256), 256>>>(h, stat, g, b, N_NODES, act);
}

extern "C" void kernel_launch(void* const* d_in, const int* in_sizes, int n_in,
                              void* d_out, int out_size) {
    (void)in_sizes; (void)n_in; (void)out_size;
    const float* x         = (const float*)d_in[0];
    const int*   esrc      = (const int*)  d_in[1];
    const int*   edst      = (const int*)  d_in[2];
    const float* W_feat    = (const float*)d_in[3];
    const float* b_feat    = (const float*)d_in[4];
    const float* g_feat    = (const float*)d_in[5];
    const float* beta_feat = (const float*)d_in[6];
    const float* gcn_W     = (const float*)d_in[7];
    const float* gcn_b     = (const float*)d_in[8];
    const float* skip_W    = (const float*)d_in[9];
    const float* skip_b    = (const float*)d_in[10];
    const float* bn_g      = (const float*)d_in[11];
    const float* bn_b      = (const float*)d_in[12];
    const float* W_c1      = (const float*)d_in[13];
    const float* b_c1      = (const float*)d_in[14];
    const float* g_c       = (const float*)d_in[15];
    const float* beta_c    = (const float*)d_in[16];
    const float* W_c2      = (const float*)d_in[17];
    const float* b_c2      = (const float*)d_in[18];
    float* out = (float*)d_out;

    float *h, *res, *m, *acc, *rsout, *rsin, *stat;
    cudaGetSymbolAddress((void**)&h,     g_h);
    cudaGetSymbolAddress((void**)&res,   g_res);
    cudaGetSymbolAddress((void**)&m,     g_m);
    cudaGetSymbolAddress((void**)&acc,   g_acc);
    cudaGetSymbolAddress((void**)&rsout, g_rs_out);
    cudaGetSymbolAddress((void**)&rsin,  g_rs_in);
    cudaGetSymbolAddress((void**)&stat,  g_stat);

    const size_t NH = (size_t)N_NODES * H_DIM;
    const int scat_blocks = ((N_EDGES + EPW - 1) / EPW + 7) / 8;  // 8 warps/block

    // --- Degree normalizers (edges fixed per call, recomputed each launch) ---
    zero4(rsout, (size_t)N_REL * N_NODES);
    zero4(rsin,  (size_t)N_REL * N_NODES);
    k_deg<<<(N_REL * N_EDGES + 255) / 256, 256>>>(esrc, edst, rsout, rsin);
    k_rsqrt_clip<<<(N_REL * N_NODES + 255) / 256, 256>>>(rsout, N_REL * N_NODES);
    k_rsqrt_clip<<<(N_REL * N_NODES + 255) / 256, 256>>>(rsin,  N_REL * N_NODES);

    // --- feat_reduce: h = relu(BN(x @ W_feat + b_feat)) ---
    run_gemm_H(x, nullptr, W_feat, b_feat, h, N_NODES, F_IN, 0);
    run_bn(h, g_feat, beta_feat, /*relu*/1, stat);

    // --- layers ---
    for (int l = 0; l < N_LAYERS; l++) {
        run_gemm_H(h, nullptr, skip_W + (size_t)l * H_DIM * H_DIM,
                   skip_b + l * H_DIM, res, N_NODES, H_DIM, 0);
        zero4(acc, NH);
        for (int r = 0; r < N_REL; r++) {
            zero4(m, NH);
            k_scatter<<<scat_blocks, 256>>>(esrc + (size_t)r * N_EDGES,
                                            edst + (size_t)r * N_EDGES,
                                            rsout + r * N_NODES, h, m);
            // acc += (m * rsqrt(din)) @ gcn_W[l,r] + gcn_b[l,r]
            run_gemm_H(m, rsin + r * N_NODES,
                       gcn_W + (size_t)(l * N_REL + r) * H_DIM * H_DIM,
                       gcn_b + (l * N_REL + r) * H_DIM, acc, N_NODES, H_DIM, 1);
        }
        // h = leaky_relu(BN(acc/3 + res))
        k_combine<<<(unsigned)((NH / 4 + 255) / 256), 256>>>(
            (const float4*)acc, (const float4*)res, (float4*)h, (int)(NH / 4));
        run_bn(h, bn_g + l * H_DIM, bn_b + l * H_DIM, /*leaky*/2, stat);
    }

    // --- head: out = relu(BN(h @ W_c1 + b_c1)) @ W_c2 + b_c2 ---
    run_gemm_H(h, nullptr, W_c1, b_c1, m, N_NODES, H_DIM, 0);
    run_bn(m, g_c, beta_c, /*relu*/1, stat);
    k_gemm<64, 4><<<dim3(1, (N_NODES + 127) / 128), 256>>>(
        m, nullptr, W_c2, b_c2, out, N_NODES, H_DIM, C_OUT, 0);
}

// round 10
// speedup vs baseline: 1.6783x; 1.6783x over previous
#include <cuda_runtime.h>
#include <cuda_bf16.h>
#include <cstdint>
#include <cstddef>

// ----------------------------------------------------------------------------
// Problem constants (HetGraphModel)
// ----------------------------------------------------------------------------
#define N_NODES  100000
#define N_EDGES  500000
#define N_REL    3
#define N_LAYERS 2
#define F_IN     300
#define H_DIM    256
#define C_OUT    23

// ----------------------------------------------------------------------------
// Scratch (device globals — no allocation allowed)
// ----------------------------------------------------------------------------
__device__ float g_h  [(size_t)N_NODES * H_DIM];
__device__ float g_res[(size_t)N_NODES * H_DIM];
__device__ float g_m  [(size_t)N_NODES * H_DIM];
__device__ float g_acc[(size_t)N_NODES * H_DIM];
__device__ float g_rs_out[N_REL * N_NODES];
__device__ float g_rs_in [N_REL * N_NODES];
__device__ float g_stat  [2 * H_DIM];
// Transposed (K-major, zero-padded) weights: 10 slots of 256 x 320
#define WT_SLOT (256 * 320)
__device__ float g_wt[10 * WT_SLOT];

// ----------------------------------------------------------------------------
// mma.sync GEMM: C[M,256] (=|+)= rowscale(A)[M,K] @ Wt[256,Kpad]^T + bias
//   Wt is K-major: Wt[n*Kpad + k], zero-padded to Kpad (Kpad % 32 == 0).
//   bf16 3-term split: D = Ah*Bh + Ah*Bl + Al*Bh  (~fp32 accuracy)
//   CTA tile 128x256, 512 threads (16 warps as 2m x 8n, warp tile 64x32),
//   BK=32 double-buffered smem, conversion fused into staging.
// ----------------------------------------------------------------------------
#define MMA_TB   512
#define MMA_BM   128
#define MMA_BN   256
#define MMA_BK   32
#define AST      40                         // smem row stride in bf16 (80 B)
#define A_AREA   (4 * MMA_BM * AST)         // [buf][hilo][row][AST]
#define B_AREA   (4 * MMA_BN * AST)
#define MMA_SMEM ((A_AREA + B_AREA) * 2)    // bytes = 122880

__device__ __forceinline__ uint32_t smem_u32(const void* p) {
    uint32_t a;
    asm("{ .reg .u64 t; cvta.to.shared.u64 t, %1; cvt.u32.u64 %0, t; }"
        : "=r"(a) : "l"(p));
    return a;
}

__device__ __forceinline__ void ldsm_x4(uint32_t* r, uint32_t addr) {
    asm volatile("ldmatrix.sync.aligned.m8n8.x4.shared.b16 {%0,%1,%2,%3}, [%4];"
                 : "=r"(r[0]), "=r"(r[1]), "=r"(r[2]), "=r"(r[3]) : "r"(addr));
}

__device__ __forceinline__ void mma_bf16(float* d, const uint32_t* a,
                                         uint32_t b0, uint32_t b1) {
    asm volatile(
        "mma.sync.aligned.m16n8k16.row.col.f32.bf16.bf16.f32 "
        "{%0,%1,%2,%3}, {%4,%5,%6,%7}, {%8,%9}, {%0,%1,%2,%3};"
        : "+f"(d[0]), "+f"(d[1]), "+f"(d[2]), "+f"(d[3])
        : "r"(a[0]), "r"(a[1]), "r"(a[2]), "r"(a[3]), "r"(b0), "r"(b1));
}

__device__ __forceinline__ void split4(float4 v, uint2& hi, uint2& lo) {
    __nv_bfloat162 h0 = __floats2bfloat162_rn(v.x, v.y);
    __nv_bfloat162 h1 = __floats2bfloat162_rn(v.z, v.w);
    float rx = v.x - __bfloat162float(h0.x);
    float ry = v.y - __bfloat162float(h0.y);
    float rz = v.z - __bfloat162float(h1.x);
    float rw = v.w - __bfloat162float(h1.y);
    __nv_bfloat162 l0 = __floats2bfloat162_rn(rx, ry);
    __nv_bfloat162 l1 = __floats2bfloat162_rn(rz, rw);
    hi = make_uint2(*reinterpret_cast<uint32_t*>(&h0), *reinterpret_cast<uint32_t*>(&h1));
    lo = make_uint2(*reinterpret_cast<uint32_t*>(&l0), *reinterpret_cast<uint32_t*>(&l1));
}

__global__ __launch_bounds__(MMA_TB)
void k_gemm_mma(const float* __restrict__ A, const float* __restrict__ rowscale,
                const float* __restrict__ Wt, const float* __restrict__ bias,
                float* __restrict__ C, int M, int K, int Kpad, int accumulate) {
    extern __shared__ __align__(16) __nv_bfloat16 sm[];
    __nv_bfloat16* As = sm;            // [2 buf][2 hilo][128][AST]
    __nv_bfloat16* Bs = sm + A_AREA;   // [2 buf][2 hilo][256][AST]

    const int tid  = threadIdx.x;
    const int wid  = tid >> 5;
    const int lane = tid & 31;
    const int m0   = blockIdx.x * MMA_BM;
    const int wm   = (wid >> 3) * 64;     // 0 or 64
    const int wn   = (wid & 7) * 32;      // 0..224

    const uint32_t su   = smem_u32(sm);
    const int lrow = lane & 15;
    const int lseg = lane >> 4;

    float acc[4][4][4];
#pragma unroll
    for (int i = 0; i < 4; i++)
#pragma unroll
        for (int j = 0; j < 4; j++)
#pragma unroll
            for (int q = 0; q < 4; q++) acc[i][j][q] = 0.f;

    const int NCH = Kpad / MMA_BK;

    // --- A prefetch (chunk 0) ---
    float4 pa[2];
#pragma unroll
    for (int i = 0; i < 2; i++) {
        int f = tid + i * MMA_TB;        // 0..1023
        int row = f >> 3, c4 = f & 7;
        int gr = m0 + row, kg = c4 * 4;
        float4 v = make_float4(0.f, 0.f, 0.f, 0.f);
        if (gr < M && kg + 4 <= K) {
            v = *reinterpret_cast<const float4*>(A + (size_t)gr * K + kg);
            if (rowscale) {
                float s = rowscale[gr];
                v.x *= s; v.y *= s; v.z *= s; v.w *= s;
            }
        }
        pa[i] = v;
    }

    for (int c = 0; c < NCH; c++) {
        const int b = c & 1;

        // --- stage A (from prefetch regs) ---
#pragma unroll
        for (int i = 0; i < 2; i++) {
            int f = tid + i * MMA_TB;
            int row = f >> 3, c4 = f & 7;
            uint2 hi, lo;
            split4(pa[i], hi, lo);
            int base = row * AST + c4 * 4;
            *reinterpret_cast<uint2*>(As + (b * 2 + 0) * MMA_BM * AST + base) = hi;
            *reinterpret_cast<uint2*>(As + (b * 2 + 1) * MMA_BM * AST + base) = lo;
        }
        // --- stage B (direct; L2-hot across CTAs) ---
#pragma unroll
        for (int i = 0; i < 4; i++) {
            int f = tid + i * MMA_TB;    // 0..2047
            int n = f >> 3, c4 = f & 7;
            float4 v = *reinterpret_cast<const float4*>(
                Wt + (size_t)n * Kpad + c * MMA_BK + c4 * 4);
            uint2 hi, lo;
            split4(v, hi, lo);
            int base = n * AST + c4 * 4;
            *reinterpret_cast<uint2*>(Bs + (b * 2 + 0) * MMA_BN * AST + base) = hi;
            *reinterpret_cast<uint2*>(Bs + (b * 2 + 1) * MMA_BN * AST + base) = lo;
        }
        __syncthreads();

        // --- prefetch A for next chunk ---
        if (c + 1 < NCH) {
#pragma unroll
            for (int i = 0; i < 2; i++) {
                int f = tid + i * MMA_TB;
                int row = f >> 3, c4 = f & 7;
                int gr = m0 + row, kg = (c + 1) * MMA_BK + c4 * 4;
                float4 v = make_float4(0.f, 0.f, 0.f, 0.f);
                if (gr < M && kg + 4 <= K) {
                    v = *reinterpret_cast<const float4*>(A + (size_t)gr * K + kg);
                    if (rowscale) {
                        float s = rowscale[gr];
                        v.x *= s; v.y *= s; v.z *= s; v.w *= s;
                    }
                }
                pa[i] = v;
            }
        }

        // --- compute on buffer b (2 ksteps of 16) ---
#pragma unroll
        for (int ks = 0; ks < 2; ks++) {
            const uint32_t klane = (uint32_t)(ks * 16 + lseg * 8);
            uint32_t af[4][4], bh[2][4], bl[2][4];
#pragma unroll
            for (int mt = 0; mt < 4; mt++) {
                uint32_t addr = su + 2u * (((b * 2 + 0) * MMA_BM + wm + mt * 16 + lrow) * AST + klane);
                ldsm_x4(af[mt], addr);
            }
#pragma unroll
            for (int p = 0; p < 2; p++) {
                uint32_t addr = su + 2u * ((A_AREA) + ((b * 2 + 0) * MMA_BN + wn + p * 16 + lrow) * AST + klane);
                ldsm_x4(bh[p], addr);
            }
#pragma unroll
            for (int p = 0; p < 2; p++) {
                uint32_t addr = su + 2u * ((A_AREA) + ((b * 2 + 1) * MMA_BN + wn + p * 16 + lrow) * AST + klane);
                ldsm_x4(bl[p], addr);
            }
#pragma unroll
            for (int mt = 0; mt < 4; mt++)
#pragma unroll
                for (int nt = 0; nt < 4; nt++) {
                    int p = nt >> 1, o = nt & 1;
                    mma_bf16(acc[mt][nt], af[mt], bh[p][o], bh[p][o + 2]);
                    mma_bf16(acc[mt][nt], af[mt], bl[p][o], bl[p][o + 2]);
                }
            // Al * Bh (reuse af regs)
#pragma unroll
            for (int mt = 0; mt < 4; mt++) {
                uint32_t addr = su + 2u * (((b * 2 + 1) * MMA_BM + wm + mt * 16 + lrow) * AST + klane);
                ldsm_x4(af[mt], addr);
            }
#pragma unroll
            for (int mt = 0; mt < 4; mt++)
#pragma unroll
                for (int nt = 0; nt < 4; nt++) {
                    int p = nt >> 1, o = nt & 1;
                    mma_bf16(acc[mt][nt], af[mt], bh[p][o], bh[p][o + 2]);
                }
        }
        __syncthreads();
    }

    // --- epilogue ---
    const int qrow = lane >> 2;
    const int qcol = (lane & 3) * 2;
#pragma unroll
    for (int mt = 0; mt < 4; mt++) {
        int r0 = m0 + wm + mt * 16 + qrow;
        int r1 = r0 + 8;
#pragma unroll
        for (int nt = 0; nt < 4; nt++) {
            int cc = wn + nt * 8 + qcol;
            float b0 = bias[cc], b1 = bias[cc + 1];
            if (r0 < M) {
                float2* p = reinterpret_cast<float2*>(C + (size_t)r0 * MMA_BN + cc);
                float2 v = make_float2(acc[mt][nt][0] + b0, acc[mt][nt][1] + b1);
                if (accumulate) { float2 o = *p; v.x += o.x; v.y += o.y; }
                *p = v;
            }
            if (r1 < M) {
                float2* p = reinterpret_cast<float2*>(C + (size_t)r1 * MMA_BN + cc);
                float2 v = make_float2(acc[mt][nt][2] + b0, acc[mt][nt][3] + b1);
                if (accumulate) { float2 o = *p; v.x += o.x; v.y += o.y; }
                *p = v;
            }
        }
    }
}

// Wt[n*Kpad + k] = (k < K) ? W[k*N + n] : 0
__global__ void k_transpose(const float* __restrict__ W, float* __restrict__ Wt,
                            int K, int N, int Kpad) {
    int idx = blockIdx.x * blockDim.x + threadIdx.x;
    if (idx >= N * Kpad) return;
    int n = idx / Kpad, k = idx % Kpad;
    Wt[idx] = (k < K) ? W[(size_t)k * N + n] : 0.f;
}

// ----------------------------------------------------------------------------
// Misc elementwise / graph kernels
// ----------------------------------------------------------------------------
__device__ __forceinline__ void red_add_v4(float4* addr, float4 v) {
    asm volatile("red.global.add.v4.f32 [%0], {%1, %2, %3, %4};"
                 :: "l"(addr), "f"(v.x), "f"(v.y), "f"(v.z), "f"(v.w)
                 : "memory");
}

__global__ void k_zero4(float4* __restrict__ p, int n4) {
    int i = blockIdx.x * blockDim.x + threadIdx.x;
    if (i < n4) p[i] = make_float4(0.f, 0.f, 0.f, 0.f);
}

__global__ void k_deg(const int* __restrict__ esrc, const int* __restrict__ edst,
                      float* __restrict__ deg_out, float* __restrict__ deg_in) {
    int i = blockIdx.x * blockDim.x + threadIdx.x;
    if (i < N_REL * N_EDGES) {
        int r = i / N_EDGES;
        atomicAdd(&deg_out[r * N_NODES + esrc[i]], 1.0f);
        atomicAdd(&deg_in [r * N_NODES + edst[i]], 1.0f);
    }
}

__global__ void k_rsqrt_clip(float* __restrict__ p, int n) {
    int i = blockIdx.x * blockDim.x + threadIdx.x;
    if (i < n) p[i] = rsqrtf(fmaxf(p[i], 1.0f));
}

// SIMT GEMM (only for the tiny C_OUT=23 head)
template <int BN_, int TN_>
__global__ __launch_bounds__(256, 2)
void k_gemm(const float* __restrict__ A, const float* __restrict__ rowscale,
            const float* __restrict__ W, const float* __restrict__ bias,
            float* __restrict__ C, int M, int K, int Nout, int accumulate) {
    constexpr int BM = 128;
    constexpr int BK = 16;
    constexpr int TM = 8;
    __shared__ float As[BK][BM + 4];
    __shared__ float Bs[BK][BN_ + 4];
    const int tid = threadIdx.x;
    const int tx = tid & 15;
    const int ty = tid >> 4;
    const int m0 = blockIdx.y * BM;
    const int n0 = blockIdx.x * BN_;
    float acc[TM][TN_];
#pragma unroll
    for (int i = 0; i < TM; i++)
#pragma unroll
        for (int j = 0; j < TN_; j++) acc[i][j] = 0.f;
    for (int k0 = 0; k0 < K; k0 += BK) {
#pragma unroll
        for (int t = 0; t < (BM * BK) / 256; t++) {
            int lin = tid + t * 256;
            int row = lin >> 4, kk = lin & 15;
            int gr = m0 + row, gk = k0 + kk;
            float v = 0.f;
            if (gr < M && gk < K) {
                v = A[(size_t)gr * K + gk];
                if (rowscale) v *= rowscale[gr];
            }
            As[kk][row] = v;
        }
#pragma unroll
        for (int t = 0; t < (BN_ * BK) / 256; t++) {
            int lin = tid + t * 256;
            int kr = lin / BN_, col = lin % BN_;
            int gk = k0 + kr, gc = n0 + col;
            Bs[kr][col] = (gk < K && gc < Nout) ? W[(size_t)gk * Nout + gc] : 0.f;
        }
        __syncthreads();
#pragma unroll
        for (int kk = 0; kk < BK; kk++) {
            float ra[TM], rb[TN_];
#pragma unroll
            for (int i = 0; i < TM; i++) ra[i] = As[kk][ty * TM + i];
#pragma unroll
            for (int j = 0; j < TN_; j++) rb[j] = Bs[kk][tx * TN_ + j];
#pragma unroll
            for (int i = 0; i < TM; i++)
#pragma unroll
                for (int j = 0; j < TN_; j++) acc[i][j] += ra[i] * rb[j];
        }
        __syncthreads();
    }
#pragma unroll
    for (int i = 0; i < TM; i++) {
        int gr = m0 + ty * TM + i;
        if (gr >= M) continue;
#pragma unroll
        for (int j = 0; j < TN_; j++) {
            int gc = n0 + tx * TN_ + j;
            if (gc >= Nout) continue;
            float v = acc[i][j] + (bias ? bias[gc] : 0.f);
            size_t idx = (size_t)gr * Nout + gc;
            if (accumulate) v += C[idx];
            C[idx] = v;
        }
    }
}

// ----------------------------------------------------------------------------
// BatchNorm
// ----------------------------------------------------------------------------
#define BN_ROWS 256
__global__ void k_bnstat(const float* __restrict__ h, float* __restrict__ stat, int M) {
    int col = threadIdx.x;
    int r0 = blockIdx.x * BN_ROWS;
    int rend = min(r0 + BN_ROWS, M);
    float s = 0.f, s2 = 0.f;
    for (int r = r0; r < rend; r++) {
        float v = h[(size_t)r * H_DIM + col];
        s += v; s2 += v * v;
    }
    atomicAdd(&stat[col], s);
    atomicAdd(&stat[H_DIM + col], s2);
}

__global__ void k_bnact(float* __restrict__ h, const float* __restrict__ stat,
                        const float* __restrict__ g, const float* __restrict__ b,
                        int M, int act) {
    size_t i = (size_t)blockIdx.x * blockDim.x + threadIdx.x;
    if (i >= (size_t)M * H_DIM) return;
    int col = (int)(i & (H_DIM - 1));
    float invM = 1.f / (float)M;
    float mean = stat[col] * invM;
    float var  = stat[H_DIM + col] * invM - mean * mean;
    float v = (h[i] - mean) * rsqrtf(var + 1e-5f) * g[col] + b[col];
    if (act == 1)      v = fmaxf(v, 0.f);
    else if (act == 2) v = (v > 0.f) ? v : 0.01f * v;
    h[i] = v;
}

__global__ void k_combine(const float4* __restrict__ acc, const float4* __restrict__ res,
                          float4* __restrict__ h, int n4) {
    int i = blockIdx.x * blockDim.x + threadIdx.x;
    if (i < n4) {
        float4 a = acc[i], r = res[i];
        h[i] = make_float4(a.x * (1.f / 3.f) + r.x, a.y * (1.f / 3.f) + r.y,
                           a.z * (1.f / 3.f) + r.z, a.w * (1.f / 3.f) + r.w);
    }
}

#define EPW 8
__global__ void k_scatter(const int* __restrict__ src, const int* __restrict__ dst,
                          const float* __restrict__ rs_out,
                          const float* __restrict__ h, float* __restrict__ m) {
    int warp = (blockIdx.x * blockDim.x + threadIdx.x) >> 5;
    int lane = threadIdx.x & 31;
    int e0 = warp * EPW;
    for (int j = 0; j < EPW; j++) {
        int e = e0 + j;
        if (e >= N_EDGES) return;
        int s = src[e];
        int d = dst[e];
        float sc = rs_out[s];
        const float4* hr = reinterpret_cast<const float4*>(h) + (size_t)s * (H_DIM / 4);
        float4*       mr = reinterpret_cast<float4*>(m)       + (size_t)d * (H_DIM / 4);
        float4 a = hr[lane];
        float4 b = hr[lane + 32];
        a.x *= sc; a.y *= sc; a.z *= sc; a.w *= sc;
        b.x *= sc; b.y *= sc; b.z *= sc; b.w *= sc;
        red_add_v4(mr + lane, a);
        red_add_v4(mr + lane + 32, b);
    }
}

// ----------------------------------------------------------------------------
// Host orchestration
// ----------------------------------------------------------------------------
static inline void zero4(float* p, size_t n) {
    int n4 = (int)(n / 4);
    k_zero4<<<(n4 + 255) / 256, 256>>>((float4*)p, n4);
}

static inline void run_mma(const float* A, const float* rs, const float* Wt,
                           const float* bias, float* C, int M, int K, int Kpad, int accum) {
    k_gemm_mma<<<(M + MMA_BM - 1) / MMA_BM, MMA_TB, MMA_SMEM>>>(
        A, rs, Wt, bias, C, M, K, Kpad, accum);
}

static inline void run_bn(float* h, const float* g, const float* b, int act, float* stat) {
    zero4(stat, 2 * H_DIM);
    k_bnstat<<<(N_NODES + BN_ROWS - 1) / BN_ROWS, H_DIM>>>(h, stat, N_NODES);
    size_t tot = (size_t)N_NODES * H_DIM;
    k_bnact<<<(unsigned)((tot + 255) / 256), 256>>>(h, stat, g, b, N_NODES, act);
}

extern "C" void kernel_launch(void* const* d_in, const int* in_sizes, int n_in,
                              void* d_out, int out_size) {
    (void)in_sizes; (void)n_in; (void)out_size;
    const float* x         = (const float*)d_in[0];
    const int*   esrc      = (const int*)  d_in[1];
    const int*   edst      = (const int*)  d_in[2];
    const float* W_feat    = (const float*)d_in[3];
    const float* b_feat    = (const float*)d_in[4];
    const float* g_feat    = (const float*)d_in[5];
    const float* beta_feat = (const float*)d_in[6];
    const float* gcn_W     = (const float*)d_in[7];
    const float* gcn_b     = (const float*)d_in[8];
    const float* skip_W    = (const float*)d_in[9];
    const float* skip_b    = (const float*)d_in[10];
    const float* bn_g      = (const float*)d_in[11];
    const float* bn_b      = (const float*)d_in[12];
    const float* W_c1      = (const float*)d_in[13];
    const float* b_c1      = (const float*)d_in[14];
    const float* g_c       = (const float*)d_in[15];
    const float* beta_c    = (const float*)d_in[16];
    const float* W_c2      = (const float*)d_in[17];
    const float* b_c2      = (const float*)d_in[18];
    float* out = (float*)d_out;

    cudaFuncSetAttribute(k_gemm_mma, cudaFuncAttributeMaxDynamicSharedMemorySize, MMA_SMEM);

    float *h, *res, *m, *acc, *rsout, *rsin, *stat, *wt;
    cudaGetSymbolAddress((void**)&h,     g_h);
    cudaGetSymbolAddress((void**)&res,   g_res);
    cudaGetSymbolAddress((void**)&m,     g_m);
    cudaGetSymbolAddress((void**)&acc,   g_acc);
    cudaGetSymbolAddress((void**)&rsout, g_rs_out);
    cudaGetSymbolAddress((void**)&rsin,  g_rs_in);
    cudaGetSymbolAddress((void**)&stat,  g_stat);
    cudaGetSymbolAddress((void**)&wt,    g_wt);

    const size_t NH = (size_t)N_NODES * H_DIM;
    const int scat_blocks = ((N_EDGES + EPW - 1) / EPW + 7) / 8;

    // --- Transpose all weights into K-major scratch ---
    // slot 0: W_feat (K=300 -> Kpad=320); 1,2: skip_W[l]; 3..8: gcn_W[l][r]; 9: W_c1
    {
        int tb = 256;
        int n320 = 256 * 320, n256 = 256 * 256;
        k_transpose<<<(n320 + tb - 1) / tb, tb>>>(W_feat, wt + 0 * WT_SLOT, F_IN, H_DIM, 320);
        for (int l = 0; l < N_LAYERS; l++)
            k_transpose<<<(n256 + tb - 1) / tb, tb>>>(skip_W + (size_t)l * H_DIM * H_DIM,
                                                      wt + (1 + l) * WT_SLOT, H_DIM, H_DIM, H_DIM);
        for (int l = 0; l < N_LAYERS; l++)
            for (int r = 0; r < N_REL; r++)
                k_transpose<<<(n256 + tb - 1) / tb, tb>>>(
                    gcn_W + (size_t)(l * N_REL + r) * H_DIM * H_DIM,
                    wt + (3 + l * N_REL + r) * WT_SLOT, H_DIM, H_DIM, H_DIM);
        k_transpose<<<(n256 + tb - 1) / tb, tb>>>(W_c1, wt + 9 * WT_SLOT, H_DIM, H_DIM, H_DIM);
    }

    // --- Degree normalizers ---
    zero4(rsout, (size_t)N_REL * N_NODES);
    zero4(rsin,  (size_t)N_REL * N_NODES);
    k_deg<<<(N_REL * N_EDGES + 255) / 256, 256>>>(esrc, edst, rsout, rsin);
    k_rsqrt_clip<<<(N_REL * N_NODES + 255) / 256, 256>>>(rsout, N_REL * N_NODES);
    k_rsqrt_clip<<<(N_REL * N_NODES + 255) / 256, 256>>>(rsin,  N_REL * N_NODES);

    // --- feat_reduce: h = relu(BN(x @ W_feat + b_feat)) ---
    run_mma(x, nullptr, wt + 0 * WT_SLOT, b_feat, h, N_NODES, F_IN, 320, 0);
    run_bn(h, g_feat, beta_feat, 1, stat);

    // --- layers ---
    for (int l = 0; l < N_LAYERS; l++) {
        run_mma(h, nullptr, wt + (1 + l) * WT_SLOT, skip_b + l * H_DIM,
                res, N_NODES, H_DIM, H_DIM, 0);
        for (int r = 0; r < N_REL; r++) {
            zero4(m, NH);
            k_scatter<<<scat_blocks, 256>>>(esrc + (size_t)r * N_EDGES,
                                            edst + (size_t)r * N_EDGES,
                                            rsout + r * N_NODES, h, m);
            run_mma(m, rsin + r * N_NODES, wt + (3 + l * N_REL + r) * WT_SLOT,
                    gcn_b + (l * N_REL + r) * H_DIM, acc, N_NODES, H_DIM, H_DIM,
                    (r > 0) ? 1 : 0);
        }
        k_combine<<<(unsigned)((NH / 4 + 255) / 256), 256>>>(
            (const float4*)acc, (const float4*)res, (float4*)h, (int)(NH / 4));
        run_bn(h, bn_g + l * H_DIM, bn_b + l * H_DIM, 2, stat);
    }

    // --- head ---
    run_mma(h, nullptr, wt + 9 * WT_SLOT, b_c1, m, N_NODES, H_DIM, H_DIM, 0);
    run_bn(m, g_c, beta_c, 1, stat);
    k_gemm<64, 4><<<dim3(1, (N_NODES + 127) / 128), 256>>>(
        m, nullptr, W_c2, b_c2, out, N_NODES, H_DIM, C_OUT, 0);
}

// round 11
// speedup vs baseline: 2.3290x; 1.3877x over previous
#include <cuda_runtime.h>
#include <cuda_bf16.h>
#include <cstdint>
#include <cstddef>

// ----------------------------------------------------------------------------
// Problem constants (HetGraphModel)
// ----------------------------------------------------------------------------
#define N_NODES  100000
#define N_EDGES  500000
#define N_REL    3
#define N_LAYERS 2
#define F_IN     300
#define H_DIM    256
#define C_OUT    23
#define NR3      (N_REL * N_NODES)      // 300000
#define E3       (N_REL * N_EDGES)      // 1500000

// ----------------------------------------------------------------------------
// Scratch (device globals — no allocation allowed)
// ----------------------------------------------------------------------------
__device__ __align__(16) float g_h   [(size_t)N_NODES * H_DIM];
__device__ __align__(16) float g_res [(size_t)N_NODES * H_DIM];
__device__ __align__(16) float g_m   [(size_t)N_NODES * H_DIM];
__device__ __align__(16) float g_mcat[(size_t)N_NODES * H_DIM * N_REL];
__device__ __align__(16) float g_rs_out[NR3];
__device__ __align__(16) float g_rs_in [NR3];
__device__ __align__(16) float g_stat  [2 * H_DIM];
__device__ __align__(16) float g_bsum  [N_LAYERS * H_DIM];
// CSR scratch
__device__ __align__(16) int g_cnt[2 * NR3];     // [0,NR3): dst counts, [NR3,2NR3): src counts
__device__ __align__(16) int g_rowstart[NR3 + 4];
__device__ __align__(16) int g_cursor[NR3];
__device__ __align__(16) int g_eidx[E3];
__device__ __align__(16) int g_bscan[512];
// Transposed K-major weights:
//   feat 256x320 @0 ; skip[l] 256x256 ; gcn_cat[l] 256x768 ; c1 256x256
#define WT_FEAT  0
#define WT_SKIP(l) (81920 + (l) * 65536)
#define WT_GCN(l)  (212992 + (l) * 196608)
#define WT_C1      606208
__device__ __align__(16) float g_wt[672000];

// ----------------------------------------------------------------------------
// mma.sync GEMM: C[M,256] = rowwise( A[M,K] @ Wt[256,Kpad]^T + bias )
//   Wt K-major: Wt[n*Kpad + k]. A row stride == K. Kpad % 32 == 0, K <= Kpad.
//   bf16 3-term split: D = Ah*Bh + Ah*Bl + Al*Bh  (~fp32 accuracy)
//   If resid != null:  C = out * scale + resid   (fused combine)
// ----------------------------------------------------------------------------
#define MMA_TB   512
#define MMA_BM   128
#define MMA_BN   256
#define MMA_BK   32
#define AST      40
#define A_AREA   (4 * MMA_BM * AST)
#define B_AREA   (4 * MMA_BN * AST)
#define MMA_SMEM ((A_AREA + B_AREA) * 2)

__device__ __forceinline__ uint32_t smem_u32(const void* p) {
    uint32_t a;
    asm("{ .reg .u64 t; cvta.to.shared.u64 t, %1; cvt.u32.u64 %0, t; }"
        : "=r"(a) : "l"(p));
    return a;
}
__device__ __forceinline__ void ldsm_x4(uint32_t* r, uint32_t addr) {
    asm volatile("ldmatrix.sync.aligned.m8n8.x4.shared.b16 {%0,%1,%2,%3}, [%4];"
                 : "=r"(r[0]), "=r"(r[1]), "=r"(r[2]), "=r"(r[3]) : "r"(addr));
}
__device__ __forceinline__ void mma_bf16(float* d, const uint32_t* a,
                                         uint32_t b0, uint32_t b1) {
    asm volatile(
        "mma.sync.aligned.m16n8k16.row.col.f32.bf16.bf16.f32 "
        "{%0,%1,%2,%3}, {%4,%5,%6,%7}, {%8,%9}, {%0,%1,%2,%3};"
        : "+f"(d[0]), "+f"(d[1]), "+f"(d[2]), "+f"(d[3])
        : "r"(a[0]), "r"(a[1]), "r"(a[2]), "r"(a[3]), "r"(b0), "r"(b1));
}
__device__ __forceinline__ void split4(float4 v, uint2& hi, uint2& lo) {
    __nv_bfloat162 h0 = __floats2bfloat162_rn(v.x, v.y);
    __nv_bfloat162 h1 = __floats2bfloat162_rn(v.z, v.w);
    float rx = v.x - __bfloat162float(h0.x);
    float ry = v.y - __bfloat162float(h0.y);
    float rz = v.z - __bfloat162float(h1.x);
    float rw = v.w - __bfloat162float(h1.y);
    __nv_bfloat162 l0 = __floats2bfloat162_rn(rx, ry);
    __nv_bfloat162 l1 = __floats2bfloat162_rn(rz, rw);
    hi = make_uint2(*reinterpret_cast<uint32_t*>(&h0), *reinterpret_cast<uint32_t*>(&h1));
    lo = make_uint2(*reinterpret_cast<uint32_t*>(&l0), *reinterpret_cast<uint32_t*>(&l1));
}

__global__ __launch_bounds__(MMA_TB)
void k_gemm_mma(const float* __restrict__ A, const float* __restrict__ Wt,
                const float* __restrict__ bias, float* __restrict__ C,
                int M, int K, int Kpad,
                const float* __restrict__ resid, float scale) {
    extern __shared__ __align__(16) __nv_bfloat16 sm[];
    __nv_bfloat16* As = sm;
    __nv_bfloat16* Bs = sm + A_AREA;

    const int tid  = threadIdx.x;
    const int wid  = tid >> 5;
    const int lane = tid & 31;
    const int m0   = blockIdx.x * MMA_BM;
    const int wm   = (wid >> 3) * 64;
    const int wn   = (wid & 7) * 32;
    const uint32_t su = smem_u32(sm);
    const int lrow = lane & 15;
    const int lseg = lane >> 4;

    float acc[4][4][4];
#pragma unroll
    for (int i = 0; i < 4; i++)
#pragma unroll
        for (int j = 0; j < 4; j++)
#pragma unroll
            for (int q = 0; q < 4; q++) acc[i][j][q] = 0.f;

    const int NCH = Kpad / MMA_BK;

    float4 pa[2];
#pragma unroll
    for (int i = 0; i < 2; i++) {
        int f = tid + i * MMA_TB;
        int row = f >> 3, c4 = f & 7;
        int gr = m0 + row, kg = c4 * 4;
        float4 v = make_float4(0.f, 0.f, 0.f, 0.f);
        if (gr < M && kg + 4 <= K)
            v = *reinterpret_cast<const float4*>(A + (size_t)gr * K + kg);
        pa[i] = v;
    }

    for (int c = 0; c < NCH; c++) {
        const int b = c & 1;
#pragma unroll
        for (int i = 0; i < 2; i++) {
            int f = tid + i * MMA_TB;
            int row = f >> 3, c4 = f & 7;
            uint2 hi, lo;
            split4(pa[i], hi, lo);
            int base = row * AST + c4 * 4;
            *reinterpret_cast<uint2*>(As + (b * 2 + 0) * MMA_BM * AST + base) = hi;
            *reinterpret_cast<uint2*>(As + (b * 2 + 1) * MMA_BM * AST + base) = lo;
        }
#pragma unroll
        for (int i = 0; i < 4; i++) {
            int f = tid + i * MMA_TB;
            int n = f >> 3, c4 = f & 7;
            float4 v = *reinterpret_cast<const float4*>(
                Wt + (size_t)n * Kpad + c * MMA_BK + c4 * 4);
            uint2 hi, lo;
            split4(v, hi, lo);
            int base = n * AST + c4 * 4;
            *reinterpret_cast<uint2*>(Bs + (b * 2 + 0) * MMA_BN * AST + base) = hi;
            *reinterpret_cast<uint2*>(Bs + (b * 2 + 1) * MMA_BN * AST + base) = lo;
        }
        __syncthreads();

        if (c + 1 < NCH) {
#pragma unroll
            for (int i = 0; i < 2; i++) {
                int f = tid + i * MMA_TB;
                int row = f >> 3, c4 = f & 7;
                int gr = m0 + row, kg = (c + 1) * MMA_BK + c4 * 4;
                float4 v = make_float4(0.f, 0.f, 0.f, 0.f);
                if (gr < M && kg + 4 <= K)
                    v = *reinterpret_cast<const float4*>(A + (size_t)gr * K + kg);
                pa[i] = v;
            }
        }

#pragma unroll
        for (int ks = 0; ks < 2; ks++) {
            const uint32_t klane = (uint32_t)(ks * 16 + lseg * 8);
            uint32_t af[4][4], bh[2][4], bl[2][4];
#pragma unroll
            for (int mt = 0; mt < 4; mt++) {
                uint32_t addr = su + 2u * (((b * 2 + 0) * MMA_BM + wm + mt * 16 + lrow) * AST + klane);
                ldsm_x4(af[mt], addr);
            }
#pragma unroll
            for (int p = 0; p < 2; p++) {
                uint32_t addr = su + 2u * ((A_AREA) + ((b * 2 + 0) * MMA_BN + wn + p * 16 + lrow) * AST + klane);
                ldsm_x4(bh[p], addr);
            }
#pragma unroll
            for (int p = 0; p < 2; p++) {
                uint32_t addr = su + 2u * ((A_AREA) + ((b * 2 + 1) * MMA_BN + wn + p * 16 + lrow) * AST + klane);
                ldsm_x4(bl[p], addr);
            }
#pragma unroll
            for (int mt = 0; mt < 4; mt++)
#pragma unroll
                for (int nt = 0; nt < 4; nt++) {
                    int p = nt >> 1, o = nt & 1;
                    mma_bf16(acc[mt][nt], af[mt], bh[p][o], bh[p][o + 2]);
                    mma_bf16(acc[mt][nt], af[mt], bl[p][o], bl[p][o + 2]);
                }
#pragma unroll
            for (int mt = 0; mt < 4; mt++) {
                uint32_t addr = su + 2u * (((b * 2 + 1) * MMA_BM + wm + mt * 16 + lrow) * AST + klane);
                ldsm_x4(af[mt], addr);
            }
#pragma unroll
            for (int mt = 0; mt < 4; mt++)
#pragma unroll
                for (int nt = 0; nt < 4; nt++) {
                    int p = nt >> 1, o = nt & 1;
                    mma_bf16(acc[mt][nt], af[mt], bh[p][o], bh[p][o + 2]);
                }
        }
        __syncthreads();
    }

    const int qrow = lane >> 2;
    const int qcol = (lane & 3) * 2;
#pragma unroll
    for (int mt = 0; mt < 4; mt++) {
        int r0 = m0 + wm + mt * 16 + qrow;
        int r1 = r0 + 8;
#pragma unroll
        for (int nt = 0; nt < 4; nt++) {
            int cc = wn + nt * 8 + qcol;
            float b0 = bias[cc], b1 = bias[cc + 1];
            if (r0 < M) {
                size_t idx = (size_t)r0 * MMA_BN + cc;
                float2 v = make_float2(acc[mt][nt][0] + b0, acc[mt][nt][1] + b1);
                if (resid) {
                    const float2 rr = *reinterpret_cast<const float2*>(resid + idx);
                    v.x = v.x * scale + rr.x; v.y = v.y * scale + rr.y;
                }
                *reinterpret_cast<float2*>(C + idx) = v;
            }
            if (r1 < M) {
                size_t idx = (size_t)r1 * MMA_BN + cc;
                float2 v = make_float2(acc[mt][nt][2] + b0, acc[mt][nt][3] + b1);
                if (resid) {
                    const float2 rr = *reinterpret_cast<const float2*>(resid + idx);
                    v.x = v.x * scale + rr.x; v.y = v.y * scale + rr.y;
                }
                *reinterpret_cast<float2*>(C + idx) = v;
            }
        }
    }
}

// Wt[n*Kpad + koff + k] = (k < Kreal) ? W[k*N + n] : 0,  k in [0, Kiter)
__global__ void k_transpose(const float* __restrict__ W, float* __restrict__ Wt,
                            int Kreal, int N, int Kpad, int Kiter, int koff) {
    int idx = blockIdx.x * blockDim.x + threadIdx.x;
    if (idx >= N * Kiter) return;
    int n = idx / Kiter, k = idx % Kiter;
    Wt[(size_t)n * Kpad + koff + k] = (k < Kreal) ? W[(size_t)k * N + n] : 0.f;
}

// ----------------------------------------------------------------------------
// CSR build + gather aggregation
// ----------------------------------------------------------------------------
__global__ void k_zero4(float4* __restrict__ p, int n4) {
    int i = blockIdx.x * blockDim.x + threadIdx.x;
    if (i < n4) p[i] = make_float4(0.f, 0.f, 0.f, 0.f);
}

__global__ void k_hist(const int* __restrict__ esrc, const int* __restrict__ edst,
                       int* __restrict__ cnt) {
    int i = blockIdx.x * blockDim.x + threadIdx.x;
    if (i < E3) {
        int r = i / N_EDGES;
        atomicAdd(&cnt[r * N_NODES + edst[i]], 1);
        atomicAdd(&cnt[NR3 + r * N_NODES + esrc[i]], 1);
    }
}

// Block-wise exclusive scan (1024 elems/block): out = local exclusive, bsum = block total
__global__ void k_scan1(const int* __restrict__ in, int* __restrict__ out,
                        int* __restrict__ bsum, int n) {
    __shared__ int ts[256];
    int tid = threadIdx.x;
    int base = blockIdx.x * 1024 + tid * 4;
    int v[4];
#pragma unroll
    for (int q = 0; q < 4; q++) v[q] = (base + q < n) ? in[base + q] : 0;
    int tot = v[0] + v[1] + v[2] + v[3];
    ts[tid] = tot;
    __syncthreads();
    for (int off = 1; off < 256; off <<= 1) {
        int x = (tid >= off) ? ts[tid - off] : 0;
        __syncthreads();
        ts[tid] += x;
        __syncthreads();
    }
    int run = ts[tid] - tot;   // exclusive prefix of this thread
#pragma unroll
    for (int q = 0; q < 4; q++) {
        if (base + q < n) out[base + q] = run;
        run += v[q];
    }
    if (tid == 255) bsum[blockIdx.x] = ts[255];
}

__global__ void k_scan2(int* __restrict__ bsum, int nb) {
    __shared__ int s[512];
    int tid = threadIdx.x;
    int orig = (tid < nb) ? bsum[tid] : 0;
    s[tid] = orig;
    __syncthreads();
    for (int off = 1; off < 512; off <<= 1) {
        int x = (tid >= off) ? s[tid - off] : 0;
        __syncthreads();
        s[tid] += x;
        __syncthreads();
    }
    if (tid < nb) bsum[tid] = s[tid] - orig;
}

__global__ void k_scan3(int* __restrict__ rowstart, const int* __restrict__ bsum,
                        const int* __restrict__ cnt, int* __restrict__ cursor,
                        float* __restrict__ rsin, float* __restrict__ rsout) {
    int i = blockIdx.x * blockDim.x + threadIdx.x;
    if (i < NR3) {
        int v = rowstart[i] + bsum[i >> 10];
        rowstart[i] = v;
        cursor[i]   = v;
        rsin[i]  = rsqrtf((float)max(cnt[i], 1));
        rsout[i] = rsqrtf((float)max(cnt[NR3 + i], 1));
    }
    if (i == 0) rowstart[NR3] = E3;
}

__global__ void k_fill(const int* __restrict__ esrc, const int* __restrict__ edst,
                       int* __restrict__ cursor, int* __restrict__ eidx) {
    int i = blockIdx.x * blockDim.x + threadIdx.x;
    if (i < E3) {
        int r = i / N_EDGES;
        int pos = atomicAdd(&cursor[r * N_NODES + edst[i]], 1);
        eidx[pos] = esrc[i];
    }
}

// One warp per (relation, node): mcat[n][r*256+c] = rs_in * sum_e rs_out[src] * h[src][c]
__global__ __launch_bounds__(256)
void k_gather(const int* __restrict__ rowstart, const int* __restrict__ eidx,
              const float* __restrict__ rsout, const float* __restrict__ rsin,
              const float* __restrict__ h, float* __restrict__ mcat) {
    int w = (blockIdx.x * blockDim.x + threadIdx.x) >> 5;
    if (w >= NR3) return;
    int lane = threadIdx.x & 31;
    int r = w / N_NODES;
    int n = w - r * N_NODES;
    int j0 = rowstart[w], j1 = rowstart[w + 1];
    float4 a = make_float4(0.f, 0.f, 0.f, 0.f);
    float4 bb = make_float4(0.f, 0.f, 0.f, 0.f);
    const float4* h4 = reinterpret_cast<const float4*>(h);
    const float* rso = rsout + r * N_NODES;
    for (int j = j0; j < j1; j++) {
        int s = eidx[j];
        float sc = rso[s];
        const float4* hr = h4 + (size_t)s * 64;
        float4 u = hr[lane];
        float4 v = hr[lane + 32];
        a.x += sc * u.x; a.y += sc * u.y; a.z += sc * u.z; a.w += sc * u.w;
        bb.x += sc * v.x; bb.y += sc * v.y; bb.z += sc * v.z; bb.w += sc * v.w;
    }
    float sn = rsin[w];
    float4* o4 = reinterpret_cast<float4*>(mcat) + (size_t)n * 192 + r * 64;
    o4[lane]      = make_float4(a.x * sn, a.y * sn, a.z * sn, a.w * sn);
    o4[lane + 32] = make_float4(bb.x * sn, bb.y * sn, bb.z * sn, bb.w * sn);
}

// bsum[l][c] = sum_r gcn_b[l][r][c]
__global__ void k_bias_sum(const float* __restrict__ gcn_b, float* __restrict__ bsum) {
    int i = blockIdx.x * blockDim.x + threadIdx.x;
    if (i < N_LAYERS * H_DIM) {
        int l = i / H_DIM, c = i - l * H_DIM;
        float s = 0.f;
        for (int r = 0; r < N_REL; r++) s += gcn_b[(l * N_REL + r) * H_DIM + c];
        bsum[i] = s;
    }
}

// ----------------------------------------------------------------------------
// BatchNorm
// ----------------------------------------------------------------------------
#define BN_ROWS 256
__global__ void k_bnstat(const float* __restrict__ h, float* __restrict__ stat, int M) {
    int col = threadIdx.x;
    int r0 = blockIdx.x * BN_ROWS;
    int rend = min(r0 + BN_ROWS, M);
    float s = 0.f, s2 = 0.f;
    for (int r = r0; r < rend; r++) {
        float v = h[(size_t)r * H_DIM + col];
        s += v; s2 += v * v;
    }
    atomicAdd(&stat[col], s);
    atomicAdd(&stat[H_DIM + col], s2);
}

__global__ void k_bnact(float* __restrict__ h, const float* __restrict__ stat,
                        const float* __restrict__ g, const float* __restrict__ b,
                        int M, int act) {
    size_t i = (size_t)blockIdx.x * blockDim.x + threadIdx.x;
    if (i >= (size_t)M * H_DIM) return;
    int col = (int)(i & (H_DIM - 1));
    float invM = 1.f / (float)M;
    float mean = stat[col] * invM;
    float var  = stat[H_DIM + col] * invM - mean * mean;
    float v = (h[i] - mean) * rsqrtf(var + 1e-5f) * g[col] + b[col];
    if (act == 1)      v = fmaxf(v, 0.f);
    else if (act == 2) v = (v > 0.f) ? v : 0.01f * v;
    h[i] = v;
}

// ----------------------------------------------------------------------------
// SIMT GEMM (only for the tiny C_OUT=23 head)
// ----------------------------------------------------------------------------
template <int BN_, int TN_>
__global__ __launch_bounds__(256, 2)
void k_gemm(const float* __restrict__ A, const float* __restrict__ W,
            const float* __restrict__ bias, float* __restrict__ C,
            int M, int K, int Nout) {
    constexpr int BM = 128;
    constexpr int BK = 16;
    constexpr int TM = 8;
    __shared__ float As[BK][BM + 4];
    __shared__ float Bs[BK][BN_ + 4];
    const int tid = threadIdx.x;
    const int tx = tid & 15;
    const int ty = tid >> 4;
    const int m0 = blockIdx.y * BM;
    const int n0 = blockIdx.x * BN_;
    float acc[TM][TN_];
#pragma unroll
    for (int i = 0; i < TM; i++)
#pragma unroll
        for (int j = 0; j < TN_; j++) acc[i][j] = 0.f;
    for (int k0 = 0; k0 < K; k0 += BK) {
#pragma unroll
        for (int t = 0; t < (BM * BK) / 256; t++) {
            int lin = tid + t * 256;
            int row = lin >> 4, kk = lin & 15;
            int gr = m0 + row, gk = k0 + kk;
            As[kk][row] = (gr < M && gk < K) ? A[(size_t)gr * K + gk] : 0.f;
        }
#pragma unroll
        for (int t = 0; t < (BN_ * BK) / 256; t++) {
            int lin = tid + t * 256;
            int kr = lin / BN_, col = lin % BN_;
            int gk = k0 + kr, gc = n0 + col;
            Bs[kr][col] = (gk < K && gc < Nout) ? W[(size_t)gk * Nout + gc] : 0.f;
        }
        __syncthreads();
#pragma unroll
        for (int kk = 0; kk < BK; kk++) {
            float ra[TM], rb[TN_];
#pragma unroll
            for (int i = 0; i < TM; i++) ra[i] = As[kk][ty * TM + i];
#pragma unroll
            for (int j = 0; j < TN_; j++) rb[j] = Bs[kk][tx * TN_ + j];
#pragma unroll
            for (int i = 0; i < TM; i++)
#pragma unroll
                for (int j = 0; j < TN_; j++) acc[i][j] += ra[i] * rb[j];
        }
        __syncthreads();
    }
#pragma unroll
    for (int i = 0; i < TM; i++) {
        int gr = m0 + ty * TM + i;
        if (gr >= M) continue;
#pragma unroll
        for (int j = 0; j < TN_; j++) {
            int gc = n0 + tx * TN_ + j;
            if (gc >= Nout) continue;
            C[(size_t)gr * Nout + gc] = acc[i][j] + bias[gc];
        }
    }
}

// ----------------------------------------------------------------------------
// Host orchestration
// ----------------------------------------------------------------------------
static inline void zero4(float* p, size_t n) {
    int n4 = (int)(n / 4);
    k_zero4<<<(n4 + 255) / 256, 256>>>((float4*)p, n4);
}

static inline void run_mma(const float* A, const float* Wt, const float* bias,
                           float* C, int M, int K, int Kpad,
                           const float* resid, float scale) {
    k_gemm_mma<<<(M + MMA_BM - 1) / MMA_BM, MMA_TB, MMA_SMEM>>>(
        A, Wt, bias, C, M, K, Kpad, resid, scale);
}

static inline void run_bn(float* h, const float* g, const float* b, int act, float* stat) {
    zero4(stat, 2 * H_DIM);
    k_bnstat<<<(N_NODES + BN_ROWS - 1) / BN_ROWS, H_DIM>>>(h, stat, N_NODES);
    size_t tot = (size_t)N_NODES * H_DIM;
    k_bnact<<<(unsigned)((tot + 255) / 256), 256>>>(h, stat, g, b, N_NODES, act);
}

extern "C" void kernel_launch(void* const* d_in, const int* in_sizes, int n_in,
                              void* d_out, int out_size) {
    (void)in_sizes; (void)n_in; (void)out_size;
    const float* x         = (const float*)d_in[0];
    const int*   esrc      = (const int*)  d_in[1];
    const int*   edst      = (const int*)  d_in[2];
    const float* W_feat    = (const float*)d_in[3];
    const float* b_feat    = (const float*)d_in[4];
    const float* g_feat    = (const float*)d_in[5];
    const float* beta_feat = (const float*)d_in[6];
    const float* gcn_W     = (const float*)d_in[7];
    const float* gcn_b     = (const float*)d_in[8];
    const float* skip_W    = (const float*)d_in[9];
    const float* skip_b    = (const float*)d_in[10];
    const float* bn_g      = (const float*)d_in[11];
    const float* bn_b      = (const float*)d_in[12];
    const float* W_c1      = (const float*)d_in[13];
    const float* b_c1      = (const float*)d_in[14];
    const float* g_c       = (const float*)d_in[15];
    const float* beta_c    = (const float*)d_in[16];
    const float* W_c2      = (const float*)d_in[17];
    const float* b_c2      = (const float*)d_in[18];
    float* out = (float*)d_out;

    cudaFuncSetAttribute(k_gemm_mma, cudaFuncAttributeMaxDynamicSharedMemorySize, MMA_SMEM);

    float *h, *res, *m, *mcat, *rsout, *rsin, *stat, *wt, *bsumf;
    int *cnt, *rowstart, *cursor, *eidx, *bscan;
    cudaGetSymbolAddress((void**)&h,     g_h);
    cudaGetSymbolAddress((void**)&res,   g_res);
    cudaGetSymbolAddress((void**)&m,     g_m);
    cudaGetSymbolAddress((void**)&mcat,  g_mcat);
    cudaGetSymbolAddress((void**)&rsout, g_rs_out);
    cudaGetSymbolAddress((void**)&rsin,  g_rs_in);
    cudaGetSymbolAddress((void**)&stat,  g_stat);
    cudaGetSymbolAddress((void**)&wt,    g_wt);
    cudaGetSymbolAddress((void**)&bsumf, g_bsum);
    cudaGetSymbolAddress((void**)&cnt,      g_cnt);
    cudaGetSymbolAddress((void**)&rowstart, g_rowstart);
    cudaGetSymbolAddress((void**)&cursor,   g_cursor);
    cudaGetSymbolAddress((void**)&eidx,     g_eidx);
    cudaGetSymbolAddress((void**)&bscan,    g_bscan);

    // --- Weight transposes (K-major) + gcn bias sums ---
    {
        const int tb = 256;
        k_transpose<<<(256 * 320 + tb - 1) / tb, tb>>>(W_feat, wt + WT_FEAT, F_IN, H_DIM, 320, 320, 0);
        for (int l = 0; l < N_LAYERS; l++) {
            k_transpose<<<(256 * 256 + tb - 1) / tb, tb>>>(
                skip_W + (size_t)l * H_DIM * H_DIM, wt + WT_SKIP(l), H_DIM, H_DIM, H_DIM, H_DIM, 0);
            for (int r = 0; r < N_REL; r++)
                k_transpose<<<(256 * 256 + tb - 1) / tb, tb>>>(
                    gcn_W + (size_t)(l * N_REL + r) * H_DIM * H_DIM,
                    wt + WT_GCN(l), H_DIM, H_DIM, N_REL * H_DIM, H_DIM, r * H_DIM);
        }
        k_transpose<<<(256 * 256 + tb - 1) / tb, tb>>>(W_c1, wt + WT_C1, H_DIM, H_DIM, H_DIM, H_DIM, 0);
        k_bias_sum<<<(N_LAYERS * H_DIM + tb - 1) / tb, tb>>>(gcn_b, bsumf);
    }

    // --- CSR build (dst-major edge lists) + degree normalizers ---
    {
        zero4((float*)cnt, 2 * NR3);
        k_hist<<<(E3 + 255) / 256, 256>>>(esrc, edst, cnt);
        const int nb = (NR3 + 1023) / 1024;   // 293
        k_scan1<<<nb, 256>>>(cnt, rowstart, bscan, NR3);
        k_scan2<<<1, 512>>>(bscan, nb);
        k_scan3<<<(NR3 + 255) / 256, 256>>>(rowstart, bscan, cnt, cursor, rsin, rsout);
        k_fill<<<(E3 + 255) / 256, 256>>>(esrc, edst, cursor, eidx);
    }

    // --- feat_reduce: h = relu(BN(x @ W_feat + b_feat)) ---
    run_mma(x, wt + WT_FEAT, b_feat, h, N_NODES, F_IN, 320, nullptr, 1.f);
    run_bn(h, g_feat, beta_feat, 1, stat);

    // --- layers ---
    const int gather_blocks = (NR3 * 32 + 255) / 256;   // 1 warp per (rel,node)
    for (int l = 0; l < N_LAYERS; l++) {
        run_mma(h, wt + WT_SKIP(l), skip_b + l * H_DIM, res, N_NODES, H_DIM, H_DIM,
                nullptr, 1.f);
        k_gather<<<gather_blocks, 256>>>(rowstart, eidx, rsout, rsin, h, mcat);
        // h = (mcat @ Wcat + sum_b)/3 + res   (fused combine)
        run_mma(mcat, wt + WT_GCN(l), bsumf + l * H_DIM, h,
                N_NODES, N_REL * H_DIM, N_REL * H_DIM, res, 1.f / 3.f);
        run_bn(h, bn_g + l * H_DIM, bn_b + l * H_DIM, 2, stat);
    }

    // --- head ---
    run_mma(h, wt + WT_C1, b_c1, m, N_NODES, H_DIM, H_DIM, nullptr, 1.f);
    run_bn(m, g_c, beta_c, 1, stat);
    k_gemm<64, 4><<<dim3(1, (N_NODES + 127) / 128), 256>>>(
        m, W_c2, b_c2, out, N_NODES, H_DIM, C_OUT);
}